// round 1
// baseline (speedup 1.0000x reference)
#include <cuda_runtime.h>

#define BNUM   4
#define SEQ    512
#define DMODEL 1024
#define HDIM   256
#define MTOT   (BNUM * SEQ)   // 2048

// Scratch for the intermediate o[b,n,h] = x @ W1^T + b1  (2048 x 256 fp32 = 2 MB)
__device__ float g_o[MTOT * HDIM];

// ----------------------------------------------------------------------------
// Stage 1: o[m,h] = sum_d X[m,d] * W1[h,d] + b1[h]
// Classic smem-tiled SGEMM, BM=BH=64, BK=16, 256 threads, 4x4 micro-tile.
// ----------------------------------------------------------------------------
__global__ __launch_bounds__(256) void stage1_kernel(
    const float* __restrict__ X,
    const float* __restrict__ W1,
    const float* __restrict__ b1)
{
    __shared__ float As[64][17];
    __shared__ float Bs[64][17];

    const int tid = threadIdx.x;
    const int m0 = blockIdx.y * 64;
    const int h0 = blockIdx.x * 64;
    const int ty = tid >> 4;        // 0..15
    const int tx = tid & 15;        // 0..15

    const int lrow = tid >> 2;      // 0..63
    const int lcol = (tid & 3) * 4; // 0,4,8,12

    float acc[4][4];
#pragma unroll
    for (int ii = 0; ii < 4; ++ii)
#pragma unroll
        for (int jj = 0; jj < 4; ++jj) acc[ii][jj] = 0.0f;

    for (int k0 = 0; k0 < DMODEL; k0 += 16) {
        float4 va = *(const float4*)(X  + (size_t)(m0 + lrow) * DMODEL + k0 + lcol);
        As[lrow][lcol + 0] = va.x; As[lrow][lcol + 1] = va.y;
        As[lrow][lcol + 2] = va.z; As[lrow][lcol + 3] = va.w;
        float4 vb = *(const float4*)(W1 + (size_t)(h0 + lrow) * DMODEL + k0 + lcol);
        Bs[lrow][lcol + 0] = vb.x; Bs[lrow][lcol + 1] = vb.y;
        Bs[lrow][lcol + 2] = vb.z; Bs[lrow][lcol + 3] = vb.w;
        __syncthreads();

#pragma unroll
        for (int k = 0; k < 16; ++k) {
            float a[4], b[4];
#pragma unroll
            for (int ii = 0; ii < 4; ++ii) a[ii] = As[ty + ii * 16][k];
#pragma unroll
            for (int jj = 0; jj < 4; ++jj) b[jj] = Bs[tx + jj * 16][k];
#pragma unroll
            for (int ii = 0; ii < 4; ++ii)
#pragma unroll
                for (int jj = 0; jj < 4; ++jj)
                    acc[ii][jj] = fmaf(a[ii], b[jj], acc[ii][jj]);
        }
        __syncthreads();
    }

#pragma unroll
    for (int ii = 0; ii < 4; ++ii) {
        const int m = m0 + ty + ii * 16;
#pragma unroll
        for (int jj = 0; jj < 4; ++jj) {
            const int h = h0 + tx + jj * 16;
            g_o[m * HDIM + h] = acc[ii][jj] + b1[h];
        }
    }
}

// ----------------------------------------------------------------------------
// Stage 2: out[b,i,j,c] = sum_h o[b,i,h] * o[b,j,h] * W2[c,h] + b2[c]
// 64x64 (i,j) tile per block, K=256 in 16-chunks, W2 resident in smem.
// Per k: hoist aw_c = o_i[h] * W2[c,h], then 2 FMAs per (i,j) pair.
// Thread mapping i = i0 + ty + ii*16, j = j0 + tx + jj*16 so that the float2
// output stores (c fastest) are fully coalesced across tx.
// ----------------------------------------------------------------------------
__global__ __launch_bounds__(256) void stage2_kernel(
    const float* __restrict__ W2,
    const float* __restrict__ b2,
    float* __restrict__ out)
{
    __shared__ float Ois[64][17];
    __shared__ float Ojs[64][17];
    __shared__ float ws0[HDIM];
    __shared__ float ws1[HDIM];

    const int tid = threadIdx.x;
    const int bb = blockIdx.z;
    const int i0 = blockIdx.y * 64;
    const int j0 = blockIdx.x * 64;
    const int ty = tid >> 4;
    const int tx = tid & 15;

    ws0[tid] = W2[tid];           // W2[0, h]
    ws1[tid] = W2[HDIM + tid];    // W2[1, h]

    const float* ob = g_o + (size_t)bb * SEQ * HDIM;

    const int lrow = tid >> 2;       // 0..63
    const int lcol = (tid & 3) * 4;  // 0,4,8,12

    float acc0[4][4], acc1[4][4];
#pragma unroll
    for (int ii = 0; ii < 4; ++ii)
#pragma unroll
        for (int jj = 0; jj < 4; ++jj) { acc0[ii][jj] = 0.0f; acc1[ii][jj] = 0.0f; }

    for (int h0 = 0; h0 < HDIM; h0 += 16) {
        float4 va = *(const float4*)(ob + (size_t)(i0 + lrow) * HDIM + h0 + lcol);
        Ois[lrow][lcol + 0] = va.x; Ois[lrow][lcol + 1] = va.y;
        Ois[lrow][lcol + 2] = va.z; Ois[lrow][lcol + 3] = va.w;
        float4 vb = *(const float4*)(ob + (size_t)(j0 + lrow) * HDIM + h0 + lcol);
        Ojs[lrow][lcol + 0] = vb.x; Ojs[lrow][lcol + 1] = vb.y;
        Ojs[lrow][lcol + 2] = vb.z; Ojs[lrow][lcol + 3] = vb.w;
        __syncthreads();

#pragma unroll
        for (int k = 0; k < 16; ++k) {
            const float w0 = ws0[h0 + k];
            const float w1 = ws1[h0 + k];
            float aw0[4], aw1[4], bv[4];
#pragma unroll
            for (int ii = 0; ii < 4; ++ii) {
                const float a = Ois[ty + ii * 16][k];
                aw0[ii] = a * w0;
                aw1[ii] = a * w1;
            }
#pragma unroll
            for (int jj = 0; jj < 4; ++jj) bv[jj] = Ojs[tx + jj * 16][k];
#pragma unroll
            for (int ii = 0; ii < 4; ++ii)
#pragma unroll
                for (int jj = 0; jj < 4; ++jj) {
                    acc0[ii][jj] = fmaf(aw0[ii], bv[jj], acc0[ii][jj]);
                    acc1[ii][jj] = fmaf(aw1[ii], bv[jj], acc1[ii][jj]);
                }
        }
        __syncthreads();
    }

    const float bias0 = b2[0];
    const float bias1 = b2[1];
#pragma unroll
    for (int ii = 0; ii < 4; ++ii) {
        const int i = i0 + ty + ii * 16;
#pragma unroll
        for (int jj = 0; jj < 4; ++jj) {
            const int j = j0 + tx + jj * 16;
            float2 v;
            v.x = acc0[ii][jj] + bias0;
            v.y = acc1[ii][jj] + bias1;
            *(float2*)(out + ((size_t)(bb * SEQ + i) * SEQ + j) * 2) = v;
        }
    }
}

extern "C" void kernel_launch(void* const* d_in, const int* in_sizes, int n_in,
                              void* d_out, int out_size)
{
    const float* x  = (const float*)d_in[0];   // [4, 512, 1024]
    const float* W1 = (const float*)d_in[1];   // [256, 1024]
    const float* b1 = (const float*)d_in[2];   // [256]
    const float* W2 = (const float*)d_in[3];   // [2, 256]
    const float* b2 = (const float*)d_in[4];   // [2]
    float* out = (float*)d_out;                // [4, 512, 512, 2]

    dim3 g1(HDIM / 64, MTOT / 64);             // (4, 32) = 128 blocks
    stage1_kernel<<<g1, 256>>>(x, W1, b1);

    dim3 g2(SEQ / 64, SEQ / 64, BNUM);         // (8, 8, 4) = 256 blocks
    stage2_kernel<<<g2, 256>>>(W2, b2, out);
}

// round 4
// speedup vs baseline: 1.7676x; 1.7676x over previous
#include <cuda_runtime.h>
#include <cuda_bf16.h>
#include <cstdint>

#define BNUM   4
#define SEQ    512
#define DMODEL 1024
#define HDIM   256
#define MTOT   2048
#define KP1    3072      // 3 * DMODEL (hi|lo|hi concat)
#define KP2    768       // 3 * HDIM
#define NJC    1024      // SEQ * 2 (j,c interleaved)

// Scratch (allocation-free __device__ globals)
__device__ __align__(16) float         g_o[MTOT * HDIM];          // 2 MB
__device__ __align__(16) __nv_bfloat16 g_Xp[MTOT * KP1];          // 12 MB
__device__ __align__(16) __nv_bfloat16 g_W1p[HDIM * KP1];         // 1.5 MB
__device__ __align__(16) __nv_bfloat16 g_Ap[MTOT * KP2];          // 3 MB
__device__ __align__(16) __nv_bfloat16 g_Bp[BNUM * NJC * KP2];    // 6 MB

// ---------------------------------------------------------------------------
// helpers
// ---------------------------------------------------------------------------
static __device__ __forceinline__ uint32_t smem_u32(const void* p) {
    uint32_t a;
    asm("{ .reg .u64 t; cvta.to.shared.u64 t, %1; cvt.u32.u64 %0, t; }"
        : "=r"(a) : "l"(p));
    return a;
}
static __device__ __forceinline__ void cp_async16(uint32_t saddr, const void* gaddr) {
    asm volatile("cp.async.cg.shared.global [%0], [%1], 16;"
                 :: "r"(saddr), "l"(gaddr) : "memory");
}
static __device__ __forceinline__ void cp_commit() {
    asm volatile("cp.async.commit_group;" ::: "memory");
}
static __device__ __forceinline__ void cp_wait1() {
    asm volatile("cp.async.wait_group 1;" ::: "memory");
}
static __device__ __forceinline__ void ldsm_x4(uint32_t* r, uint32_t addr) {
    asm volatile("ldmatrix.sync.aligned.m8n8.x4.shared.b16 {%0,%1,%2,%3}, [%4];"
                 : "=r"(r[0]), "=r"(r[1]), "=r"(r[2]), "=r"(r[3]) : "r"(addr));
}
static __device__ __forceinline__ void mma16816(float* d, const uint32_t* a,
                                                uint32_t b0, uint32_t b1) {
    asm volatile(
        "mma.sync.aligned.m16n8k16.row.col.f32.bf16.bf16.f32 "
        "{%0,%1,%2,%3}, {%4,%5,%6,%7}, {%8,%9}, {%0,%1,%2,%3};"
        : "+f"(d[0]), "+f"(d[1]), "+f"(d[2]), "+f"(d[3])
        : "r"(a[0]), "r"(a[1]), "r"(a[2]), "r"(a[3]), "r"(b0), "r"(b1));
}
static __device__ __forceinline__ void st_bf2(__nv_bfloat16* p, __nv_bfloat16 a, __nv_bfloat16 b) {
    __nv_bfloat162 t; t.x = a; t.y = b;
    *(__nv_bfloat162*)p = t;
}
static __device__ __forceinline__ void split1(float v, __nv_bfloat16& h, __nv_bfloat16& l) {
    h = __float2bfloat16_rn(v);
    l = __float2bfloat16_rn(v - __bfloat162float(h));
}

// ---------------------------------------------------------------------------
// Prep 1: split X -> [hi|lo|hi], W1 -> [hi|hi|lo]
// ---------------------------------------------------------------------------
__global__ __launch_bounds__(256) void split_xw(const float* __restrict__ X,
                                                const float* __restrict__ W1) {
    const int NX4 = MTOT * DMODEL / 4;   // 524288
    int idx = blockIdx.x * 256 + threadIdx.x;
    if (idx < NX4) {
        int r = idx >> 8;
        int k = (idx & 255) * 4;
        float4 v = *(const float4*)(X + (size_t)r * DMODEL + k);
        __nv_bfloat16 h0,h1,h2,h3,l0,l1,l2,l3;
        split1(v.x,h0,l0); split1(v.y,h1,l1); split1(v.z,h2,l2); split1(v.w,h3,l3);
        __nv_bfloat16* base = g_Xp + (size_t)r * KP1 + k;
        st_bf2(base,              h0,h1); st_bf2(base+2,              h2,h3);
        st_bf2(base+DMODEL,       l0,l1); st_bf2(base+DMODEL+2,       l2,l3);
        st_bf2(base+2*DMODEL,     h0,h1); st_bf2(base+2*DMODEL+2,     h2,h3);
    } else {
        int i2 = idx - NX4;
        if (i2 >= HDIM * DMODEL / 4) return;
        int r = i2 >> 8;
        int k = (i2 & 255) * 4;
        float4 v = *(const float4*)(W1 + (size_t)r * DMODEL + k);
        __nv_bfloat16 h0,h1,h2,h3,l0,l1,l2,l3;
        split1(v.x,h0,l0); split1(v.y,h1,l1); split1(v.z,h2,l2); split1(v.w,h3,l3);
        __nv_bfloat16* base = g_W1p + (size_t)r * KP1 + k;
        st_bf2(base,              h0,h1); st_bf2(base+2,              h2,h3);
        st_bf2(base+DMODEL,       h0,h1); st_bf2(base+DMODEL+2,       h2,h3);
        st_bf2(base+2*DMODEL,     l0,l1); st_bf2(base+2*DMODEL+2,     l2,l3);
    }
}

// ---------------------------------------------------------------------------
// Prep 2: from o (fp32): A' = [o_hi|o_lo|o_hi]; B' rows jc=2j+c: v=o_j*w_c,
// [v_hi|v_hi|v_lo]
// ---------------------------------------------------------------------------
__global__ __launch_bounds__(256) void prep_o(const float* __restrict__ W2) {
    int idx = blockIdx.x * 256 + threadIdx.x;       // over 2048*64
    int m = idx >> 6;
    int h = (idx & 63) * 4;
    float4 o4 = *(const float4*)(g_o + (size_t)m * HDIM + h);
    __nv_bfloat16 h0,h1,h2,h3,l0,l1,l2,l3;
    split1(o4.x,h0,l0); split1(o4.y,h1,l1); split1(o4.z,h2,l2); split1(o4.w,h3,l3);
    __nv_bfloat16* abase = g_Ap + (size_t)m * KP2 + h;
    st_bf2(abase,          h0,h1); st_bf2(abase+2,          h2,h3);
    st_bf2(abase+HDIM,     l0,l1); st_bf2(abase+HDIM+2,     l2,l3);
    st_bf2(abase+2*HDIM,   h0,h1); st_bf2(abase+2*HDIM+2,   h2,h3);

    int b = m >> 9, j = m & 511;
    float4 w0 = *(const float4*)(W2 + h);
    float4 w1 = *(const float4*)(W2 + HDIM + h);
#pragma unroll
    for (int c = 0; c < 2; ++c) {
        float4 w = c ? w1 : w0;
        float4 v;
        v.x = o4.x * w.x; v.y = o4.y * w.y; v.z = o4.z * w.z; v.w = o4.w * w.w;
        __nv_bfloat16 vh0,vh1,vh2,vh3,vl0,vl1,vl2,vl3;
        split1(v.x,vh0,vl0); split1(v.y,vh1,vl1); split1(v.z,vh2,vl2); split1(v.w,vh3,vl3);
        __nv_bfloat16* bbase = g_Bp + ((size_t)b * NJC + 2 * j + c) * KP2 + h;
        st_bf2(bbase,          vh0,vh1); st_bf2(bbase+2,          vh2,vh3);
        st_bf2(bbase+HDIM,     vh0,vh1); st_bf2(bbase+HDIM+2,     vh2,vh3);
        st_bf2(bbase+2*HDIM,   vl0,vl1); st_bf2(bbase+2*HDIM+2,   vl2,vl3);
    }
}

// ---------------------------------------------------------------------------
// mma.sync bf16 TN GEMM: D[64,64] = A[64,K] * B[64,K]^T, 3-stage cp.async
// pipeline, 128 threads, warp tile 32x32 (m16n8k16).
// smem tile: 64 rows x 128B, XOR-swizzled 16B chunks (chunk ^= row&7).
// mode 0: C = g_o + b1[col]   (Kp = KP1, A = g_Xp, B = g_W1p)
// mode 1: C = out + b2[col&1] (Kp = KP2, A = g_Ap,  B = g_Bp)
// ---------------------------------------------------------------------------
#define BM   64
#define BN   64
#define BK   64
#define ASB  8192                     // stage bytes: 64 rows * 128B
#define BOFFB (3 * ASB)               // B region offset: 24576
#define SMEM_SZ (6 * ASB)             // 49152 bytes == default 48KB limit

__global__ __launch_bounds__(128) void gemm_kernel(int mode,
                                                   const float* __restrict__ bias,
                                                   float* __restrict__ outp) {
    extern __shared__ char smem[];
    const uint32_t sbase = smem_u32(smem);
    const int tid = threadIdx.x;
    const int wid = tid >> 5, lane = tid & 31;
    const int wm = wid & 1, wn = wid >> 1;           // 2x2 warp grid
    const int m0 = blockIdx.y * BM, n0 = blockIdx.x * BN, bz = blockIdx.z;

    const __nv_bfloat16* Ab;
    const __nv_bfloat16* Bb;
    int Kp;
    if (mode == 0) { Ab = g_Xp + (size_t)m0 * KP1; Bb = g_W1p + (size_t)n0 * KP1; Kp = KP1; }
    else           { Ab = g_Ap + ((size_t)(bz * SEQ + m0)) * KP2;
                     Bb = g_Bp + ((size_t)(bz * NJC + n0)) * KP2; Kp = KP2; }
    const int NC = Kp >> 6;   // K chunks of 64

    // per-thread load mapping: row = tid/2, 4x16B chunks starting at (tid&1)*64B
    const int lrow = tid >> 1;
    const int lcb  = (tid & 1) * 4;                  // first chunk index (16B units)
    const int lxr  = lrow & 7;                       // swizzle key

    float acc[2][4][4];
#pragma unroll
    for (int mt = 0; mt < 2; ++mt)
#pragma unroll
        for (int j = 0; j < 4; ++j)
#pragma unroll
            for (int e = 0; e < 4; ++e) acc[mt][j][e] = 0.0f;

    // prologue: stages 0,1
#pragma unroll
    for (int s = 0; s < 2; ++s) {
        const __nv_bfloat16* Ag = Ab + s * BK + (size_t)lrow * Kp + lcb * 8;
        const __nv_bfloat16* Bg = Bb + s * BK + (size_t)lrow * Kp + lcb * 8;
        const uint32_t rowA = sbase + s * ASB + lrow * 128;
        const uint32_t rowB = rowA + BOFFB;
#pragma unroll
        for (int q = 0; q < 4; ++q) {
            const uint32_t sw = (uint32_t)(((lcb + q) ^ lxr) << 4);
            cp_async16(rowA + sw, Ag + q * 8);
            cp_async16(rowB + sw, Bg + q * 8);
        }
        cp_commit();
    }

    // ldmatrix row bases (per thread); row+16 shares the same xor (16 % 8 == 0)
    const int arow = wm * 32 + (lane & 15);
    const int brow = wn * 32 + (lane & 15);
    const int kl   = lane >> 4;                      // 0 or 1 (k chunk half)
    const uint32_t aRow = sbase + (uint32_t)(arow * 128);
    const uint32_t bRow = sbase + BOFFB + (uint32_t)(brow * 128);
    const int axr = arow & 7, bxr = brow & 7;

    for (int kc = 0; kc < NC; ++kc) {
        cp_wait1();
        __syncthreads();

        const int s = kc % 3;
        const uint32_t aS = aRow + (uint32_t)(s * ASB);
        const uint32_t bS = bRow + (uint32_t)(s * ASB);
#pragma unroll
        for (int ks = 0; ks < 4; ++ks) {
            const int c16 = ks * 2 + kl;
            const uint32_t swa = (uint32_t)((c16 ^ axr) << 4);
            const uint32_t swb = (uint32_t)((c16 ^ bxr) << 4);
            uint32_t a0[4], a1[4], b0[4], b1[4];
            ldsm_x4(a0, aS + swa);
            ldsm_x4(a1, aS + 16 * 128 + swa);
            ldsm_x4(b0, bS + swb);
            ldsm_x4(b1, bS + 16 * 128 + swb);
            mma16816(acc[0][0], a0, b0[0], b0[2]);
            mma16816(acc[0][1], a0, b0[1], b0[3]);
            mma16816(acc[0][2], a0, b1[0], b1[2]);
            mma16816(acc[0][3], a0, b1[1], b1[3]);
            mma16816(acc[1][0], a1, b0[0], b0[2]);
            mma16816(acc[1][1], a1, b0[1], b0[3]);
            mma16816(acc[1][2], a1, b1[0], b1[2]);
            mma16816(acc[1][3], a1, b1[1], b1[3]);
        }

        if (kc + 2 < NC) {
            const int s2 = (kc + 2) % 3;
            const __nv_bfloat16* Ag = Ab + (kc + 2) * BK + (size_t)lrow * Kp + lcb * 8;
            const __nv_bfloat16* Bg = Bb + (kc + 2) * BK + (size_t)lrow * Kp + lcb * 8;
            const uint32_t rowA = sbase + s2 * ASB + lrow * 128;
            const uint32_t rowB = rowA + BOFFB;
#pragma unroll
            for (int q = 0; q < 4; ++q) {
                const uint32_t sw = (uint32_t)(((lcb + q) ^ lxr) << 4);
                cp_async16(rowA + sw, Ag + q * 8);
                cp_async16(rowB + sw, Bg + q * 8);
            }
        }
        cp_commit();
    }

    // epilogue
    const int row0 = m0 + wm * 32 + (lane >> 2);
    const int col0 = n0 + wn * 32 + (lane & 3) * 2;
    float bv0 = 0.f, bv1 = 0.f;
    if (mode == 1) { bv0 = bias[0]; bv1 = bias[1]; }
#pragma unroll
    for (int mt = 0; mt < 2; ++mt) {
#pragma unroll
        for (int j = 0; j < 4; ++j) {
            const int col = col0 + j * 8;
            const int r0 = row0 + mt * 16;
            if (mode == 0) {
                const float b0v = bias[col], b1v = bias[col + 1];
                float2 v0; v0.x = acc[mt][j][0] + b0v; v0.y = acc[mt][j][1] + b1v;
                float2 v1; v1.x = acc[mt][j][2] + b0v; v1.y = acc[mt][j][3] + b1v;
                *(float2*)(g_o + (size_t)r0 * HDIM + col)       = v0;
                *(float2*)(g_o + (size_t)(r0 + 8) * HDIM + col) = v1;
            } else {
                float2 v0; v0.x = acc[mt][j][0] + bv0; v0.y = acc[mt][j][1] + bv1;
                float2 v1; v1.x = acc[mt][j][2] + bv0; v1.y = acc[mt][j][3] + bv1;
                float* base = outp + ((size_t)bz * SEQ) * NJC;
                *(float2*)(base + (size_t)r0 * NJC + col)       = v0;
                *(float2*)(base + (size_t)(r0 + 8) * NJC + col) = v1;
            }
        }
    }
}

// ---------------------------------------------------------------------------
extern "C" void kernel_launch(void* const* d_in, const int* in_sizes, int n_in,
                              void* d_out, int out_size)
{
    const float* x  = (const float*)d_in[0];   // [4, 512, 1024]
    const float* W1 = (const float*)d_in[1];   // [256, 1024]
    const float* b1 = (const float*)d_in[2];   // [256]
    const float* W2 = (const float*)d_in[3];   // [2, 256]
    const float* b2 = (const float*)d_in[4];   // [2]
    float* out = (float*)d_out;                // [4, 512, 512, 2]

    // Prep 1: split inputs
    split_xw<<<2304, 256>>>(x, W1);

    // Stage 1 GEMM: o = x @ W1^T + b1   (M=2048, N=256, K'=3072)
    gemm_kernel<<<dim3(HDIM / BN, MTOT / BM, 1), 128, SMEM_SZ>>>(0, b1, nullptr);

    // Prep 2: split o and fold W2 into B operand
    prep_o<<<512, 256>>>(W2);

    // Stage 2 GEMM: out[b,i,jc] = A @ B'^T + b2  (M=512, N=1024, K'=768) x4
    gemm_kernel<<<dim3(NJC / BN, SEQ / BM, BNUM), 128, SMEM_SZ>>>(1, b2, out);
}

// round 5
// speedup vs baseline: 2.3881x; 1.3511x over previous
#include <cuda_runtime.h>
#include <cuda_bf16.h>
#include <cstdint>

#define BNUM   4
#define SEQ    512
#define DMODEL 1024
#define HDIM   256
#define MTOT   2048
#define KP1    3072      // 3 * DMODEL (hi|lo|hi concat)
#define KP2    768       // 3 * HDIM
#define NJC    1024      // SEQ * 2 (j,c interleaved)
#define NSPLIT 4         // split-K factor for stage-1 GEMM
#define KSPL   (KP1 / NSPLIT)   // 768 — same NC as gemm2

// Scratch (allocation-free __device__ globals)
__device__ __align__(16) float         g_p1[NSPLIT * MTOT * HDIM];  // 8 MB partials
__device__ __align__(16) __nv_bfloat16 g_Xp[MTOT * KP1];            // 12 MB
__device__ __align__(16) __nv_bfloat16 g_W1p[HDIM * KP1];           // 1.5 MB
__device__ __align__(16) __nv_bfloat16 g_Ap[MTOT * KP2];            // 3 MB
__device__ __align__(16) __nv_bfloat16 g_Bp[BNUM * NJC * KP2];      // 6 MB

// ---------------------------------------------------------------------------
// helpers
// ---------------------------------------------------------------------------
static __device__ __forceinline__ uint32_t smem_u32(const void* p) {
    uint32_t a;
    asm("{ .reg .u64 t; cvta.to.shared.u64 t, %1; cvt.u32.u64 %0, t; }"
        : "=r"(a) : "l"(p));
    return a;
}
static __device__ __forceinline__ void cp_async16(uint32_t saddr, const void* gaddr) {
    asm volatile("cp.async.cg.shared.global [%0], [%1], 16;"
                 :: "r"(saddr), "l"(gaddr) : "memory");
}
static __device__ __forceinline__ void cp_commit() {
    asm volatile("cp.async.commit_group;" ::: "memory");
}
static __device__ __forceinline__ void cp_wait1() {
    asm volatile("cp.async.wait_group 1;" ::: "memory");
}
static __device__ __forceinline__ void cp_wait0() {
    asm volatile("cp.async.wait_group 0;" ::: "memory");
}
static __device__ __forceinline__ void ldsm_x4(uint32_t* r, uint32_t addr) {
    asm volatile("ldmatrix.sync.aligned.m8n8.x4.shared.b16 {%0,%1,%2,%3}, [%4];"
                 : "=r"(r[0]), "=r"(r[1]), "=r"(r[2]), "=r"(r[3]) : "r"(addr));
}
static __device__ __forceinline__ void mma16816(float* d, const uint32_t* a,
                                                uint32_t b0, uint32_t b1) {
    asm volatile(
        "mma.sync.aligned.m16n8k16.row.col.f32.bf16.bf16.f32 "
        "{%0,%1,%2,%3}, {%4,%5,%6,%7}, {%8,%9}, {%0,%1,%2,%3};"
        : "+f"(d[0]), "+f"(d[1]), "+f"(d[2]), "+f"(d[3])
        : "r"(a[0]), "r"(a[1]), "r"(a[2]), "r"(a[3]), "r"(b0), "r"(b1));
}
static __device__ __forceinline__ void st_bf2(__nv_bfloat16* p, __nv_bfloat16 a, __nv_bfloat16 b) {
    __nv_bfloat162 t; t.x = a; t.y = b;
    *(__nv_bfloat162*)p = t;
}
static __device__ __forceinline__ void split1(float v, __nv_bfloat16& h, __nv_bfloat16& l) {
    h = __float2bfloat16_rn(v);
    l = __float2bfloat16_rn(v - __bfloat162float(h));
}

// ---------------------------------------------------------------------------
// Prep 1: split X -> [hi|lo|hi], W1 -> [hi|hi|lo]
// ---------------------------------------------------------------------------
__global__ __launch_bounds__(256) void split_xw(const float* __restrict__ X,
                                                const float* __restrict__ W1) {
    const int NX4 = MTOT * DMODEL / 4;   // 524288
    int idx = blockIdx.x * 256 + threadIdx.x;
    if (idx < NX4) {
        int r = idx >> 8;
        int k = (idx & 255) * 4;
        float4 v = *(const float4*)(X + (size_t)r * DMODEL + k);
        __nv_bfloat16 h0,h1,h2,h3,l0,l1,l2,l3;
        split1(v.x,h0,l0); split1(v.y,h1,l1); split1(v.z,h2,l2); split1(v.w,h3,l3);
        __nv_bfloat16* base = g_Xp + (size_t)r * KP1 + k;
        st_bf2(base,              h0,h1); st_bf2(base+2,              h2,h3);
        st_bf2(base+DMODEL,       l0,l1); st_bf2(base+DMODEL+2,       l2,l3);
        st_bf2(base+2*DMODEL,     h0,h1); st_bf2(base+2*DMODEL+2,     h2,h3);
    } else {
        int i2 = idx - NX4;
        if (i2 >= HDIM * DMODEL / 4) return;
        int r = i2 >> 8;
        int k = (i2 & 255) * 4;
        float4 v = *(const float4*)(W1 + (size_t)r * DMODEL + k);
        __nv_bfloat16 h0,h1,h2,h3,l0,l1,l2,l3;
        split1(v.x,h0,l0); split1(v.y,h1,l1); split1(v.z,h2,l2); split1(v.w,h3,l3);
        __nv_bfloat16* base = g_W1p + (size_t)r * KP1 + k;
        st_bf2(base,              h0,h1); st_bf2(base+2,              h2,h3);
        st_bf2(base+DMODEL,       h0,h1); st_bf2(base+DMODEL+2,       h2,h3);
        st_bf2(base+2*DMODEL,     l0,l1); st_bf2(base+2*DMODEL+2,     l2,l3);
    }
}

// ---------------------------------------------------------------------------
// Prep 2 (fused reduce): o = sum_s p1[s] + b1; A' = [o_hi|o_lo|o_hi];
// B' rows jc=2j+c: v=o*w_c, [v_hi|v_hi|v_lo]
// ---------------------------------------------------------------------------
__global__ __launch_bounds__(256) void prep_o(const float* __restrict__ W2,
                                              const float* __restrict__ b1) {
    int idx = blockIdx.x * 256 + threadIdx.x;       // over 2048*64
    int m = idx >> 6;
    int h = (idx & 63) * 4;

    float4 o4 = *(const float4*)(g_p1 + (size_t)m * HDIM + h);
#pragma unroll
    for (int s = 1; s < NSPLIT; ++s) {
        float4 p = *(const float4*)(g_p1 + ((size_t)s * MTOT + m) * HDIM + h);
        o4.x += p.x; o4.y += p.y; o4.z += p.z; o4.w += p.w;
    }
    float4 bb = *(const float4*)(b1 + h);
    o4.x += bb.x; o4.y += bb.y; o4.z += bb.z; o4.w += bb.w;

    __nv_bfloat16 h0,h1,h2,h3,l0,l1,l2,l3;
    split1(o4.x,h0,l0); split1(o4.y,h1,l1); split1(o4.z,h2,l2); split1(o4.w,h3,l3);
    __nv_bfloat16* abase = g_Ap + (size_t)m * KP2 + h;
    st_bf2(abase,          h0,h1); st_bf2(abase+2,          h2,h3);
    st_bf2(abase+HDIM,     l0,l1); st_bf2(abase+HDIM+2,     l2,l3);
    st_bf2(abase+2*HDIM,   h0,h1); st_bf2(abase+2*HDIM+2,   h2,h3);

    int b = m >> 9, j = m & 511;
    float4 w0 = *(const float4*)(W2 + h);
    float4 w1 = *(const float4*)(W2 + HDIM + h);
#pragma unroll
    for (int c = 0; c < 2; ++c) {
        float4 w = c ? w1 : w0;
        float4 v;
        v.x = o4.x * w.x; v.y = o4.y * w.y; v.z = o4.z * w.z; v.w = o4.w * w.w;
        __nv_bfloat16 vh0,vh1,vh2,vh3,vl0,vl1,vl2,vl3;
        split1(v.x,vh0,vl0); split1(v.y,vh1,vl1); split1(v.z,vh2,vl2); split1(v.w,vh3,vl3);
        __nv_bfloat16* bbase = g_Bp + ((size_t)b * NJC + 2 * j + c) * KP2 + h;
        st_bf2(bbase,          vh0,vh1); st_bf2(bbase+2,          vh2,vh3);
        st_bf2(bbase+HDIM,     vh0,vh1); st_bf2(bbase+HDIM+2,     vh2,vh3);
        st_bf2(bbase+2*HDIM,   vl0,vl1); st_bf2(bbase+2*HDIM+2,   vl2,vl3);
    }
}

// ---------------------------------------------------------------------------
// mma.sync bf16 TN GEMM: D[64,64] = A[64,K] * B[64,K]^T, 3-stage cp.async
// pipeline, 256 threads / 8 warps. Warps 0-3 consume ks 0-1 of each stage,
// warps 4-7 consume ks 2-3 (in-CTA K-split); partials combined via smem.
// mode 0: C = g_p1[z]          (A = g_Xp, B = g_W1p, k-window z*768..)
// mode 1: C = out + b2[col&1]  (A = g_Ap, B = g_Bp)
// ---------------------------------------------------------------------------
#define BM   64
#define BN   64
#define BK   64
#define ASB  8192                     // stage bytes: 64 rows * 128B
#define BOFFB (3 * ASB)               // B region offset: 24576
#define SMEM_SZ (6 * ASB)             // 49152 bytes == default 48KB limit
#define NC   12                       // 768 / 64 for both gemms

__global__ __launch_bounds__(256, 4) void gemm_kernel(int mode,
                                                      const float* __restrict__ bias,
                                                      float* __restrict__ outp) {
    extern __shared__ char smem[];
    const uint32_t sbase = smem_u32(smem);
    const int tid = threadIdx.x;
    const int wid = tid >> 5, lane = tid & 31;
    const int grp = wid >> 2;                        // k-group 0/1
    const int wm = wid & 1, wn = (wid >> 1) & 1;     // 2x2 warp grid per group
    const int m0 = blockIdx.y * BM, n0 = blockIdx.x * BN, bz = blockIdx.z;

    const __nv_bfloat16* Ab;
    const __nv_bfloat16* Bb;
    int Kp;
    if (mode == 0) { Ab = g_Xp + (size_t)m0 * KP1 + bz * KSPL;
                     Bb = g_W1p + (size_t)n0 * KP1 + bz * KSPL; Kp = KP1; }
    else           { Ab = g_Ap + ((size_t)(bz * SEQ + m0)) * KP2;
                     Bb = g_Bp + ((size_t)(bz * NJC + n0)) * KP2; Kp = KP2; }

    // per-thread load mapping: row = tid/4, 2x16B chunks starting at (tid&3)*32B
    const int lrow = tid >> 2;
    const int lcb  = (tid & 3) * 2;                  // first chunk index (16B units)
    const int lxr  = lrow & 7;                       // swizzle key

    float acc[2][4][4];
#pragma unroll
    for (int mt = 0; mt < 2; ++mt)
#pragma unroll
        for (int j = 0; j < 4; ++j)
#pragma unroll
            for (int e = 0; e < 4; ++e) acc[mt][j][e] = 0.0f;

    // prologue: stages 0,1
#pragma unroll
    for (int s = 0; s < 2; ++s) {
        const __nv_bfloat16* Ag = Ab + s * BK + (size_t)lrow * Kp + lcb * 8;
        const __nv_bfloat16* Bg = Bb + s * BK + (size_t)lrow * Kp + lcb * 8;
        const uint32_t rowA = sbase + s * ASB + lrow * 128;
        const uint32_t rowB = rowA + BOFFB;
#pragma unroll
        for (int q = 0; q < 2; ++q) {
            const uint32_t sw = (uint32_t)(((lcb + q) ^ lxr) << 4);
            cp_async16(rowA + sw, Ag + q * 8);
            cp_async16(rowB + sw, Bg + q * 8);
        }
        cp_commit();
    }

    // ldmatrix row bases; row+16 shares the same xor (16 % 8 == 0)
    const int arow = wm * 32 + (lane & 15);
    const int brow = wn * 32 + (lane & 15);
    const int kl   = lane >> 4;                      // 0 or 1 (16B half within k16)
    const uint32_t aRow = sbase + (uint32_t)(arow * 128);
    const uint32_t bRow = sbase + BOFFB + (uint32_t)(brow * 128);
    const int axr = arow & 7, bxr = brow & 7;

    for (int kc = 0; kc < NC; ++kc) {
        cp_wait1();
        __syncthreads();

        const int s = kc % 3;
        const uint32_t aS = aRow + (uint32_t)(s * ASB);
        const uint32_t bS = bRow + (uint32_t)(s * ASB);
#pragma unroll
        for (int ksi = 0; ksi < 2; ++ksi) {
            const int c16 = (grp * 2 + ksi) * 2 + kl;
            const uint32_t swa = (uint32_t)((c16 ^ axr) << 4);
            const uint32_t swb = (uint32_t)((c16 ^ bxr) << 4);
            uint32_t a0[4], a1[4], b0[4], b1[4];
            ldsm_x4(a0, aS + swa);
            ldsm_x4(a1, aS + 16 * 128 + swa);
            ldsm_x4(b0, bS + swb);
            ldsm_x4(b1, bS + 16 * 128 + swb);
            mma16816(acc[0][0], a0, b0[0], b0[2]);
            mma16816(acc[0][1], a0, b0[1], b0[3]);
            mma16816(acc[0][2], a0, b1[0], b1[2]);
            mma16816(acc[0][3], a0, b1[1], b1[3]);
            mma16816(acc[1][0], a1, b0[0], b0[2]);
            mma16816(acc[1][1], a1, b0[1], b0[3]);
            mma16816(acc[1][2], a1, b1[0], b1[2]);
            mma16816(acc[1][3], a1, b1[1], b1[3]);
        }

        if (kc + 2 < NC) {
            const int s2 = (kc + 2) % 3;
            const __nv_bfloat16* Ag = Ab + (kc + 2) * BK + (size_t)lrow * Kp + lcb * 8;
            const __nv_bfloat16* Bg = Bb + (kc + 2) * BK + (size_t)lrow * Kp + lcb * 8;
            const uint32_t rowA = sbase + s2 * ASB + lrow * 128;
            const uint32_t rowB = rowA + BOFFB;
#pragma unroll
            for (int q = 0; q < 2; ++q) {
                const uint32_t sw = (uint32_t)(((lcb + q) ^ lxr) << 4);
                cp_async16(rowA + sw, Ag + q * 8);
                cp_async16(rowB + sw, Bg + q * 8);
            }
        }
        cp_commit();
    }

    // ---- combine the two k-groups through smem, then store (group 0) ----
    cp_wait0();
    __syncthreads();

    float* sC = (float*)smem;                        // 64 x 66 fp32 = 16.9KB
    const int rr = lane >> 2;                        // 0..7
    const int cc0 = wn * 32 + (lane & 3) * 2;        // col base

    if (grp == 1) {
#pragma unroll
        for (int mt = 0; mt < 2; ++mt)
#pragma unroll
            for (int j = 0; j < 4; ++j) {
                const int r0 = wm * 32 + rr + mt * 16;
                const int c  = cc0 + j * 8;
                float2 v0; v0.x = acc[mt][j][0]; v0.y = acc[mt][j][1];
                float2 v1; v1.x = acc[mt][j][2]; v1.y = acc[mt][j][3];
                *(float2*)(sC + r0 * 66 + c)       = v0;
                *(float2*)(sC + (r0 + 8) * 66 + c) = v1;
            }
    }
    __syncthreads();

    if (grp == 0) {
        const int row0 = m0 + wm * 32 + rr;
        const int col0 = n0 + cc0;
        float bv0 = 0.f, bv1 = 0.f;
        if (mode == 1) { bv0 = bias[0]; bv1 = bias[1]; }
#pragma unroll
        for (int mt = 0; mt < 2; ++mt) {
#pragma unroll
            for (int j = 0; j < 4; ++j) {
                const int lr0 = wm * 32 + rr + mt * 16;
                const int lc  = cc0 + j * 8;
                float2 p0 = *(float2*)(sC + lr0 * 66 + lc);
                float2 p1 = *(float2*)(sC + (lr0 + 8) * 66 + lc);
                const int col = col0 + j * 8;
                const int r0 = row0 + mt * 16;
                if (mode == 0) {
                    float* base = g_p1 + (size_t)bz * MTOT * HDIM;
                    float2 v0; v0.x = acc[mt][j][0] + p0.x; v0.y = acc[mt][j][1] + p0.y;
                    float2 v1; v1.x = acc[mt][j][2] + p1.x; v1.y = acc[mt][j][3] + p1.y;
                    *(float2*)(base + (size_t)r0 * HDIM + col)       = v0;
                    *(float2*)(base + (size_t)(r0 + 8) * HDIM + col) = v1;
                } else {
                    float2 v0; v0.x = acc[mt][j][0] + p0.x + bv0; v0.y = acc[mt][j][1] + p0.y + bv1;
                    float2 v1; v1.x = acc[mt][j][2] + p1.x + bv0; v1.y = acc[mt][j][3] + p1.y + bv1;
                    float* base = outp + ((size_t)bz * SEQ) * NJC;
                    *(float2*)(base + (size_t)r0 * NJC + col)       = v0;
                    *(float2*)(base + (size_t)(r0 + 8) * NJC + col) = v1;
                }
            }
        }
    }
}

// ---------------------------------------------------------------------------
extern "C" void kernel_launch(void* const* d_in, const int* in_sizes, int n_in,
                              void* d_out, int out_size)
{
    const float* x  = (const float*)d_in[0];   // [4, 512, 1024]
    const float* W1 = (const float*)d_in[1];   // [256, 1024]
    const float* b1 = (const float*)d_in[2];   // [256]
    const float* W2 = (const float*)d_in[3];   // [2, 256]
    const float* b2 = (const float*)d_in[4];   // [2]
    float* out = (float*)d_out;                // [4, 512, 512, 2]

    // Prep 1: split inputs
    split_xw<<<2304, 256>>>(x, W1);

    // Stage 1 GEMM (split-K=4): p1[z] = x @ W1^T over k-window z
    gemm_kernel<<<dim3(HDIM / BN, MTOT / BM, NSPLIT), 256, SMEM_SZ>>>(0, nullptr, nullptr);

    // Prep 2: fused reduce(+b1) + split + fold W2 into B operand
    prep_o<<<512, 256>>>(W2, b1);

    // Stage 2 GEMM: out[b,i,jc] = A @ B'^T + b2  (M=512, N=1024, K'=768) x4
    gemm_kernel<<<dim3(NJC / BN, SEQ / BM, BNUM), 256, SMEM_SZ>>>(1, b2, out);
}